// round 4
// baseline (speedup 1.0000x reference)
#include <cuda_runtime.h>
#include <math.h>

#define SEQ 640
#define BATCH 40
#define DIN 8
#define DL 64
#define NH 4
#define DH 48
#define EMB 192
#define ROWS (SEQ*BATCH)   // 25600

typedef unsigned long long ull;

// ---------------- scratch ----------------
__device__ float d_gx[ROWS * 256];
__device__ float d_seq[ROWS * DL];
__device__ float d_q[ROWS * EMB];
__device__ float d_k[ROWS * EMB];
__device__ float d_v[ROWS * EMB];
__device__ float d_att[ROWS * EMB];

__device__ __forceinline__ float sigf(float x) { return 1.f / (1.f + __expf(-x)); }
__device__ __forceinline__ float tanhfast(float x) { return 2.f / (1.f + __expf(-2.f * x)) - 1.f; }

__device__ __forceinline__ ull fma2(ull a, ull b, ull c) {
    ull d;
    asm("fma.rn.f32x2 %0, %1, %2, %3;" : "=l"(d) : "l"(a), "l"(b), "l"(c));
    return d;
}
__device__ __forceinline__ float lo32(ull u) { return __uint_as_float((unsigned)u); }
__device__ __forceinline__ float hi32(ull u) { return __uint_as_float((unsigned)(u >> 32)); }
__device__ __forceinline__ float sum2(ull u) { return lo32(u) + hi32(u); }
__device__ __forceinline__ ull dup2(float s) {
    ull d;
    asm("mov.b64 %0, {%1, %1};" : "=l"(d) : "r"(__float_as_uint(s)));
    return d;
}

// ---------------- K1: embed + gates_x ----------------
__global__ void __launch_bounds__(256) k1_embed_gates(
    const float* __restrict__ hist, const float* __restrict__ W1,
    const float* __restrict__ b1, const float* __restrict__ W_ih,
    const float* __restrict__ b_ih, const float* __restrict__ b_hh)
{
    __shared__ __align__(16) float xs[8 * 32];
    int tid = threadIdx.x;

    ull w2[16];
    const ull* wp = (const ull*)(W_ih + tid * 32);
#pragma unroll
    for (int i = 0; i < 16; i++) w2[i] = wp[i];
    float bsum = b_ih[tid] + b_hh[tid];

    int rl = tid >> 5, j = tid & 31;
    const float* hp = hist + (blockIdx.x * 8 + rl) * DIN;
    float acc = b1[j];
#pragma unroll
    for (int f = 0; f < DIN; f++) acc = fmaf(hp[f], W1[j * DIN + f], acc);
    xs[rl * 32 + j] = acc > 0.f ? acc : expm1f(acc);
    __syncthreads();

#pragma unroll
    for (int r = 0; r < 8; r++) {
        const ulonglong2* xv = (const ulonglong2*)(xs + r * 32);
        ull s0 = 0, s1 = 0;
#pragma unroll
        for (int q = 0; q < 8; q++) {
            ulonglong2 x2 = xv[q];
            s0 = fma2(x2.x, w2[2 * q], s0);
            s1 = fma2(x2.y, w2[2 * q + 1], s1);
        }
        d_gx[(blockIdx.x * 8 + r) * 256 + tid] = bsum + (sum2(s0) + sum2(s1));
    }
}

// ---------------- K2: LSTM recurrence ----------------
__global__ void __launch_bounds__(256) k2_lstm(const float* __restrict__ W_hh)
{
    __shared__ __align__(16) float h_s[64];
    __shared__ float gate_s[256];
    int t = threadIdx.x;
    int b = blockIdx.x;
    int grp = t >> 6;

    ull w2[32];
    const ull* wp = (const ull*)(W_hh + t * 64);
#pragma unroll
    for (int i = 0; i < 32; i++) w2[i] = wp[i];

    float c = 0.f;
    if (t < 64) h_s[t] = 0.f;
    float gx_c = d_gx[(0 * BATCH + b) * 256 + t];
    float gx_n = d_gx[(1 * BATCH + b) * 256 + t];
    __syncthreads();

    for (int step = 0; step < SEQ; step++) {
        float gx_f = 0.f;
        if (step + 2 < SEQ) gx_f = d_gx[((step + 2) * BATCH + b) * 256 + t];

        const ulonglong2* h2 = (const ulonglong2*)h_s;
        ull a0 = 0, a1 = 0, a2 = 0, a3 = 0;
#pragma unroll
        for (int i = 0; i < 8; i++) {
            ulonglong2 p = h2[2 * i], q = h2[2 * i + 1];
            a0 = fma2(p.x, w2[4 * i + 0], a0);
            a1 = fma2(p.y, w2[4 * i + 1], a1);
            a2 = fma2(q.x, w2[4 * i + 2], a2);
            a3 = fma2(q.y, w2[4 * i + 3], a3);
        }
        float gate = gx_c + ((sum2(a0) + sum2(a1)) + (sum2(a2) + sum2(a3)));
        float act = (grp == 2) ? tanhfast(gate) : sigf(gate);
        gate_s[t] = act;
        __syncthreads();

        if (t < 64) {
            float ai = act;                 // own gate (group 0 = input gate)
            float af = gate_s[64 + t];
            float ag = gate_s[128 + t];
            float ao = gate_s[192 + t];
            c = af * c + ai * ag;
            float hv = ao * tanhfast(c);
            h_s[t] = hv;
            d_seq[(step * BATCH + b) * 64 + t] = hv;
        }
        __syncthreads();
        gx_c = gx_n; gx_n = gx_f;
    }
}

// ---------------- K3: QKV GEMM 128x64 tile, 256 thr, 8x4/thread ----------------
__global__ void __launch_bounds__(256) k3_qkv(
    const float* __restrict__ Wq, const float* __restrict__ bq,
    const float* __restrict__ Wk, const float* __restrict__ bk,
    const float* __restrict__ Wv, const float* __restrict__ bv)
{
    __shared__ __align__(16) float As[16 * 256];
    __shared__ __align__(16) float Bs[16 * 128];
    int tid = threadIdx.x;
    int mt = blockIdx.x, nt = blockIdx.y;

    const float* W; const float* bias; float* out; int n0;
    if (nt < 3)      { W = Wq; bias = bq; out = d_q; n0 = nt * 64; }
    else if (nt < 6) { W = Wk; bias = bk; out = d_k; n0 = (nt - 3) * 64; }
    else             { W = Wv; bias = bv; out = d_v; n0 = (nt - 6) * 64; }

    int tx = tid & 15, ty = tid >> 4;
    int m0 = ty * 8, nn0 = tx * 4;
    ull acc[8][4] = {};

    for (int kc = 0; kc < 2; kc++) {
#pragma unroll
        for (int i = 0; i < 4; i++) {
            int e = tid + i * 256;
            int r = e & 127, c4 = e >> 7;
            float4 v = *(const float4*)&d_seq[(mt * 128 + r) * 64 + kc * 32 + c4 * 4];
            *(float2*)&As[(c4 * 2) * 256 + r * 2] = make_float2(v.x, v.y);
            *(float2*)&As[(c4 * 2 + 1) * 256 + r * 2] = make_float2(v.z, v.w);
        }
#pragma unroll
        for (int i = 0; i < 2; i++) {
            int e = tid + i * 256;
            int r = e & 63, c4 = e >> 6;
            float4 v = *(const float4*)&W[(n0 + r) * 64 + kc * 32 + c4 * 4];
            *(float2*)&Bs[(c4 * 2) * 128 + r * 2] = make_float2(v.x, v.y);
            *(float2*)&Bs[(c4 * 2 + 1) * 128 + r * 2] = make_float2(v.z, v.w);
        }
        __syncthreads();
#pragma unroll
        for (int k2 = 0; k2 < 16; k2++) {
            ulonglong2 a01 = *(const ulonglong2*)&As[k2 * 256 + m0 * 2];
            ulonglong2 a23 = *(const ulonglong2*)&As[k2 * 256 + m0 * 2 + 4];
            ulonglong2 a45 = *(const ulonglong2*)&As[k2 * 256 + m0 * 2 + 8];
            ulonglong2 a67 = *(const ulonglong2*)&As[k2 * 256 + m0 * 2 + 12];
            ulonglong2 b01 = *(const ulonglong2*)&Bs[k2 * 128 + nn0 * 2];
            ulonglong2 b23 = *(const ulonglong2*)&Bs[k2 * 128 + nn0 * 2 + 4];
            ull av[8] = {a01.x, a01.y, a23.x, a23.y, a45.x, a45.y, a67.x, a67.y};
            ull bv_[4] = {b01.x, b01.y, b23.x, b23.y};
#pragma unroll
            for (int i = 0; i < 8; i++)
#pragma unroll
                for (int j = 0; j < 4; j++)
                    acc[i][j] = fma2(av[i], bv_[j], acc[i][j]);
        }
        __syncthreads();
    }
    float4 bv4 = *(const float4*)&bias[n0 + nn0];
#pragma unroll
    for (int i = 0; i < 8; i++) {
        int row = mt * 128 + m0 + i;
        float4 o;
        o.x = sum2(acc[i][0]) + bv4.x; o.y = sum2(acc[i][1]) + bv4.y;
        o.z = sum2(acc[i][2]) + bv4.z; o.w = sum2(acc[i][3]) + bv4.w;
        *(float4*)&out[row * EMB + n0 + nn0] = o;
    }
}

// ---------------- K4: attention, (i,ct) lane mapping, parallel softmax ----------------
__global__ void __launch_bounds__(160) k4_attn()
{
    __shared__ __align__(16) float qs[40 * 52];
    __shared__ __align__(16) float ks[40 * 52];
    __shared__ __align__(16) float vs[40 * 52];
    __shared__ float ss[40 * 41];
    int t = blockIdx.x, h = blockIdx.y;
    int tid = threadIdx.x;

#pragma unroll
    for (int ii = 0; ii < 9; ii++) {
        int e = tid + ii * 160;
        int arr = e / 480, idx = e - arr * 480;
        int r = idx / 12, c4 = idx - r * 12;
        const float* src = arr == 0 ? d_q : (arr == 1 ? d_k : d_v);
        float* dst = arr == 0 ? qs : (arr == 1 ? ks : vs);
        float4 v = *(const float4*)&src[(t * BATCH + r) * EMB + h * DH + c4 * 4];
        *(float4*)&dst[r * 52 + c4 * 4] = v;
    }
    __syncthreads();

    int i = tid >> 2;      // row 0..39, 4 consecutive lanes per row
    int ct = tid & 3;      // chunk 0..3
    int j0 = ct * 10;

    // S = Q K^T / 8 : thread handles row i vs 10 K-rows, result kept in regs
    float sreg[10];
    {
        ull acc[10] = {};
#pragma unroll
        for (int kk = 0; kk < 12; kk++) {
            ulonglong2 q2 = *(const ulonglong2*)&qs[i * 52 + kk * 4];
#pragma unroll
            for (int jj = 0; jj < 10; jj++) {
                ulonglong2 k2v = *(const ulonglong2*)&ks[(j0 + jj) * 52 + kk * 4];
                acc[jj] = fma2(q2.x, k2v.x, acc[jj]);
                acc[jj] = fma2(q2.y, k2v.y, acc[jj]);
            }
        }
#pragma unroll
        for (int jj = 0; jj < 10; jj++) sreg[jj] = sum2(acc[jj]) * 0.125f;
    }

    // softmax across the 4 lanes of each row (lanes 4i..4i+3)
    {
        float m = sreg[0];
#pragma unroll
        for (int jj = 1; jj < 10; jj++) m = fmaxf(m, sreg[jj]);
        m = fmaxf(m, __shfl_xor_sync(0xFFFFFFFFu, m, 1));
        m = fmaxf(m, __shfl_xor_sync(0xFFFFFFFFu, m, 2));
        float sum = 0.f;
#pragma unroll
        for (int jj = 0; jj < 10; jj++) { sreg[jj] = __expf(sreg[jj] - m); sum += sreg[jj]; }
        sum += __shfl_xor_sync(0xFFFFFFFFu, sum, 1);
        sum += __shfl_xor_sync(0xFFFFFFFFu, sum, 2);
        float inv = 1.f / sum;
#pragma unroll
        for (int jj = 0; jj < 10; jj++) ss[i * 41 + j0 + jj] = sreg[jj] * inv;
    }
    __syncthreads();

    // O = P V : thread (i, ct): row i, d-chunk ct*12
    {
        int d0 = ct * 12;
        ull acc[6] = {};
#pragma unroll
        for (int j = 0; j < 40; j++) {
            ull sp = dup2(ss[i * 41 + j]);
            ulonglong2 v0 = *(const ulonglong2*)&vs[j * 52 + d0];
            ulonglong2 v1 = *(const ulonglong2*)&vs[j * 52 + d0 + 4];
            ulonglong2 v2 = *(const ulonglong2*)&vs[j * 52 + d0 + 8];
            acc[0] = fma2(sp, v0.x, acc[0]);
            acc[1] = fma2(sp, v0.y, acc[1]);
            acc[2] = fma2(sp, v1.x, acc[2]);
            acc[3] = fma2(sp, v1.y, acc[3]);
            acc[4] = fma2(sp, v2.x, acc[4]);
            acc[5] = fma2(sp, v2.y, acc[5]);
        }
        float* op = &d_att[(t * BATCH + i) * EMB + h * DH + d0];
        float4 o0, o1, o2;
        o0.x = lo32(acc[0]); o0.y = hi32(acc[0]); o0.z = lo32(acc[1]); o0.w = hi32(acc[1]);
        o1.x = lo32(acc[2]); o1.y = hi32(acc[2]); o1.z = lo32(acc[3]); o1.w = hi32(acc[3]);
        o2.x = lo32(acc[4]); o2.y = hi32(acc[4]); o2.z = lo32(acc[5]); o2.w = hi32(acc[5]);
        *(float4*)&op[0] = o0;
        *(float4*)&op[4] = o1;
        *(float4*)&op[8] = o2;
    }
}

// ---------------- K5: fused GLU GEMM (M64 x N128) + GLU + residual + LayerNorm ----------------
__global__ void __launch_bounds__(256) k5_glu_ln(
    const float* __restrict__ Wa, const float* __restrict__ ba,
    const float* __restrict__ Wg, const float* __restrict__ bg,
    const float* __restrict__ gamma, const float* __restrict__ beta,
    float* __restrict__ out)
{
    // buf reused: stage phase = As(2048) + Bs(4096); epilogue phase = os(64*136)
    __shared__ __align__(16) float buf[64 * 136];
    float* As = buf;              // [k2][m-pair], 16 x 128
    float* Bs = buf + 16 * 128;   // [k2][n-pair], 16 x 256
    float* os = buf;              // [64][136]
    int tid = threadIdx.x;
    int mt = blockIdx.x;

    int tx = tid & 15, ty = tid >> 4;
    int m0 = ty * 4, n0 = tx * 8;
    ull acc[4][4] = {};

    for (int kc = 0; kc < 6; kc++) {
#pragma unroll
        for (int i = 0; i < 1; i++) {
            // A: 64 rows x 32 k = 512 float4; 2 per thread
#pragma unroll
            for (int s = 0; s < 2; s++) {
                int e = tid + s * 256;
                int r = e & 63, c4 = e >> 6;
                float4 v = *(const float4*)&d_att[(mt * 64 + r) * EMB + kc * 32 + c4 * 4];
                *(float2*)&As[(c4 * 2) * 128 + r * 2] = make_float2(v.x, v.y);
                *(float2*)&As[(c4 * 2 + 1) * 128 + r * 2] = make_float2(v.z, v.w);
            }
            // B: 128 n-rows x 32 k = 1024 float4; 4 per thread
#pragma unroll
            for (int s = 0; s < 4; s++) {
                int e = tid + s * 256;
                int r = e & 127, c4 = e >> 7;
                const float* Wsrc = (r < 64) ? &Wa[r * EMB] : &Wg[(r - 64) * EMB];
                float4 v = *(const float4*)&Wsrc[kc * 32 + c4 * 4];
                *(float2*)&Bs[(c4 * 2) * 256 + r * 2] = make_float2(v.x, v.y);
                *(float2*)&Bs[(c4 * 2 + 1) * 256 + r * 2] = make_float2(v.z, v.w);
            }
        }
        __syncthreads();
#pragma unroll
        for (int k2 = 0; k2 < 16; k2++) {
            ulonglong2 a01 = *(const ulonglong2*)&As[k2 * 128 + m0 * 2];
            ulonglong2 a23 = *(const ulonglong2*)&As[k2 * 128 + m0 * 2 + 4];
            ulonglong2 b01 = *(const ulonglong2*)&Bs[k2 * 256 + n0 * 2];
            ulonglong2 b23 = *(const ulonglong2*)&Bs[k2 * 256 + n0 * 2 + 4];
            ulonglong2 b45 = *(const ulonglong2*)&Bs[k2 * 256 + n0 * 2 + 8];
            ulonglong2 b67 = *(const ulonglong2*)&Bs[k2 * 256 + n0 * 2 + 12];
            ull av[4] = {a01.x, a01.y, a23.x, a23.y};
            ull bv_[4] = {b01.x, b01.y, b23.x, b23.y};  // n0..n0+3 pairs? NOTE: 8 n-floats = 4 ull
            // 8 n floats = 4 ull: b01,b23 hold first 4... use all four vars:
            ull bw_[4] = {b45.x, b45.y, b67.x, b67.y};
#pragma unroll
            for (int i = 0; i < 4; i++) {
#pragma unroll
                for (int j = 0; j < 2; j++) {
                    acc[i][j] = fma2(av[i], bv_[2 * j], acc[i][j]);       // placeholder, fixed below
                }
            }
            // full 4x4: n pairs are bv_[0..3] for floats n0..n0+7? Each ull = 1 n-value's k-pair.
            // Correct mapping: Bs row stores per-n k-pairs: n-th ull = &Bs[k2*256 + n*2].
            // b01 = n0,n0+1 ; b23 = n0+2,n0+3 ; b45 = n0+4,n0+5 ; b67 = n0+6,n0+7
#pragma unroll
            for (int i = 0; i < 4; i++) {
                acc[i][0] = fma2(av[i], bv_[1], acc[i][0]); // dummy to keep structure — replaced below
            }
        }
        __syncthreads();
    }
    // NOTE: the loop above is structurally wrong — real implementation below.
    (void)os;
    // fallback: never reached
}

// ---- correct K5 (the above stub is unused; this is the launched kernel) ----
__global__ void __launch_bounds__(256) k5_glu_ln_v2(
    const float* __restrict__ Wa, const float* __restrict__ ba,
    const float* __restrict__ Wg, const float* __restrict__ bg,
    const float* __restrict__ gamma, const float* __restrict__ beta,
    float* __restrict__ out)
{
    __shared__ __align__(16) float buf[64 * 136];
    float* As = buf;              // 16 x 128
    float* Bs = buf + 16 * 128;   // 16 x 256
    float* os = buf;              // 64 x 136 (reused after compute)
    int tid = threadIdx.x;
    int mt = blockIdx.x;

    int tx = tid & 15, ty = tid >> 4;
    int m0 = ty * 4, n0 = tx * 8;
    ull acc[4][4] = {};   // 4 m-rows x 8 n-floats (4 ull, each = one n's k-pair accumulation? no:)
    // acc[i][j] accumulates output (m0+i, n0+2j, n0+2j+1)? No — with k-paired fma2,
    // acc[i][j] = k-paired partial for SINGLE output (m0+i, n0+j)… we need 8 n → acc[4][8] too big.
    // Use n-float4 style like k3: acc[i][j] for j in 0..3 covers n0..n0+3 only; n-tile = 4.
    // => n0 = tx*4, 16 tx covers 64; need 128 n → split: ty covers m AND high-n? Simpler:
    // tile: 256 thr as (tx 0..31 → n0 = tx*4 covers 128) x (ty 0..7 → m0 = ty*8 covers 64).
    tx = tid & 31; ty = tid >> 5;
    m0 = ty * 8; n0 = tx * 4;
    ull acc2[8][4] = {};

    for (int kc = 0; kc < 6; kc++) {
#pragma unroll
        for (int s = 0; s < 2; s++) {
            int e = tid + s * 256;
            int r = e & 63, c4 = e >> 6;
            float4 v = *(const float4*)&d_att[(mt * 64 + r) * EMB + kc * 32 + c4 * 4];
            *(float2*)&As[(c4 * 2) * 128 + r * 2] = make_float2(v.x, v.y);
            *(float2*)&As[(c4 * 2 + 1) * 128 + r * 2] = make_float2(v.z, v.w);
        }
#pragma unroll
        for (int s = 0; s < 4; s++) {
            int e = tid + s * 256;
            int r = e & 127, c4 = e >> 7;
            const float* Wsrc = (r < 64) ? &Wa[r * EMB] : &Wg[(r - 64) * EMB];
            float4 v = *(const float4*)&Wsrc[kc * 32 + c4 * 4];
            *(float2*)&Bs[(c4 * 2) * 256 + r * 2] = make_float2(v.x, v.y);
            *(float2*)&Bs[(c4 * 2 + 1) * 256 + r * 2] = make_float2(v.z, v.w);
        }
        __syncthreads();
#pragma unroll
        for (int k2 = 0; k2 < 16; k2++) {
            ulonglong2 a01 = *(const ulonglong2*)&As[k2 * 128 + m0 * 2];
            ulonglong2 a23 = *(const ulonglong2*)&As[k2 * 128 + m0 * 2 + 4];
            ulonglong2 a45 = *(const ulonglong2*)&As[k2 * 128 + m0 * 2 + 8];
            ulonglong2 a67 = *(const ulonglong2*)&As[k2 * 128 + m0 * 2 + 12];
            ulonglong2 b01 = *(const ulonglong2*)&Bs[k2 * 256 + n0 * 2];
            ulonglong2 b23 = *(const ulonglong2*)&Bs[k2 * 256 + n0 * 2 + 4];
            ull av[8] = {a01.x, a01.y, a23.x, a23.y, a45.x, a45.y, a67.x, a67.y};
            ull bv_[4] = {b01.x, b01.y, b23.x, b23.y};
#pragma unroll
            for (int i = 0; i < 8; i++)
#pragma unroll
                for (int j = 0; j < 4; j++)
                    acc2[i][j] = fma2(av[i], bv_[j], acc2[i][j]);
        }
        __syncthreads();
    }

    // write o (+bias) into os[64][136]
    float4 bv4;
    if (n0 < 64) bv4 = *(const float4*)&ba[n0];
    else         bv4 = *(const float4*)&bg[n0 - 64];
#pragma unroll
    for (int i = 0; i < 8; i++) {
        float4 o;
        o.x = sum2(acc2[i][0]) + bv4.x; o.y = sum2(acc2[i][1]) + bv4.y;
        o.z = sum2(acc2[i][2]) + bv4.z; o.w = sum2(acc2[i][3]) + bv4.w;
        *(float4*)&os[(m0 + i) * 136 + n0] = o;
    }
    __syncthreads();

    // GLU + residual + LayerNorm: thread = (row r = tid>>2, col-chunk q = tid&3 of 16)
    {
        int r = tid >> 2, q = tid & 3;
        int c0 = q * 16;
        int grow = mt * 64 + r;
        float y[16];
        float s = 0.f, s2 = 0.f;
#pragma unroll
        for (int c = 0; c < 16; c++) {
            int j = c0 + c;
            float a = os[r * 136 + j];
            float g = os[r * 136 + 64 + j];
            float yv = d_seq[grow * 64 + j] + a * sigf(g);
            y[c] = yv; s += yv; s2 += yv * yv;
        }
        s += __shfl_xor_sync(0xFFFFFFFFu, s, 1);
        s += __shfl_xor_sync(0xFFFFFFFFu, s, 2);
        s2 += __shfl_xor_sync(0xFFFFFFFFu, s2, 1);
        s2 += __shfl_xor_sync(0xFFFFFFFFu, s2, 2);
        float mu = s * (1.f / 64.f);
        float var = s2 * (1.f / 64.f) - mu * mu;
        float inv = rsqrtf(var + 1e-5f);
#pragma unroll
        for (int c = 0; c < 16; c++) {
            int j = c0 + c;
            out[grow * 64 + j] = (y[c] - mu) * inv * gamma[j] + beta[j];
        }
    }
}

// ---------------- launch ----------------
extern "C" void kernel_launch(void* const* d_in, const int* in_sizes, int n_in,
                              void* d_out, int out_size)
{
    const float* hist = (const float*)d_in[0];
    const float* W1   = (const float*)d_in[2];
    const float* b1   = (const float*)d_in[3];
    const float* W_ih = (const float*)d_in[4];
    const float* W_hh = (const float*)d_in[5];
    const float* b_ih = (const float*)d_in[6];
    const float* b_hh = (const float*)d_in[7];
    const float* Wq   = (const float*)d_in[8];
    const float* bq   = (const float*)d_in[9];
    const float* Wk   = (const float*)d_in[10];
    const float* bk   = (const float*)d_in[11];
    const float* Wv   = (const float*)d_in[12];
    const float* bv   = (const float*)d_in[13];
    const float* Wa   = (const float*)d_in[14];
    const float* ba   = (const float*)d_in[15];
    const float* Wg   = (const float*)d_in[16];
    const float* bg   = (const float*)d_in[17];
    const float* gamma= (const float*)d_in[18];
    const float* beta = (const float*)d_in[19];
    float* out = (float*)d_out;

    k1_embed_gates<<<ROWS / 8, 256>>>(hist, W1, b1, W_ih, b_ih, b_hh);
    k2_lstm<<<BATCH, 256>>>(W_hh);
    k3_qkv<<<dim3(ROWS / 128, 9), 256>>>(Wq, bq, Wk, bk, Wv, bv);
    k4_attn<<<dim3(SEQ, NH), 160>>>();
    k5_glu_ln_v2<<<ROWS / 64, 256>>>(Wa, ba, Wg, bg, gamma, beta, out);
}

// round 5
// speedup vs baseline: 1.1973x; 1.1973x over previous
#include <cuda_runtime.h>
#include <math.h>

#define SEQ 640
#define BATCH 40
#define DIN 8
#define DL 64
#define NH 4
#define DH 48
#define EMB 192
#define ROWS (SEQ*BATCH)   // 25600

typedef unsigned long long ull;

// ---------------- scratch ----------------
__device__ float d_gx[ROWS * 256];
__device__ float d_seq[ROWS * DL];
__device__ float d_q[ROWS * EMB];
__device__ float d_k[ROWS * EMB];
__device__ float d_v[ROWS * EMB];
__device__ float d_att[ROWS * EMB];

__device__ __forceinline__ float sigf(float x) { return 1.f / (1.f + __expf(-x)); }

// MUFU.TANH path (sm_75+): 1 MUFU instead of ex2+rcp chains
__device__ __forceinline__ float tanh_mufu(float x) {
    float y;
    asm("tanh.approx.f32 %0, %1;" : "=f"(y) : "f"(x));
    return y;
}
__device__ __forceinline__ float sig_mufu(float x) {
    return fmaf(tanh_mufu(0.5f * x), 0.5f, 0.5f);
}

__device__ __forceinline__ ull fma2(ull a, ull b, ull c) {
    ull d;
    asm("fma.rn.f32x2 %0, %1, %2, %3;" : "=l"(d) : "l"(a), "l"(b), "l"(c));
    return d;
}
__device__ __forceinline__ float lo32(ull u) { return __uint_as_float((unsigned)u); }
__device__ __forceinline__ float hi32(ull u) { return __uint_as_float((unsigned)(u >> 32)); }
__device__ __forceinline__ float sum2(ull u) { return lo32(u) + hi32(u); }
__device__ __forceinline__ ull dup2(float s) {
    ull d;
    asm("mov.b64 %0, {%1, %1};" : "=l"(d) : "r"(__float_as_uint(s)));
    return d;
}

// ---------------- K1: embed + gates_x ----------------
__global__ void __launch_bounds__(256) k1_embed_gates(
    const float* __restrict__ hist, const float* __restrict__ W1,
    const float* __restrict__ b1, const float* __restrict__ W_ih,
    const float* __restrict__ b_ih, const float* __restrict__ b_hh)
{
    __shared__ __align__(16) float xs[8 * 32];
    int tid = threadIdx.x;

    ull w2[16];
    const ull* wp = (const ull*)(W_ih + tid * 32);
#pragma unroll
    for (int i = 0; i < 16; i++) w2[i] = wp[i];
    float bsum = b_ih[tid] + b_hh[tid];

    int rl = tid >> 5, j = tid & 31;
    const float* hp = hist + (blockIdx.x * 8 + rl) * DIN;
    float acc = b1[j];
#pragma unroll
    for (int f = 0; f < DIN; f++) acc = fmaf(hp[f], W1[j * DIN + f], acc);
    xs[rl * 32 + j] = acc > 0.f ? acc : expm1f(acc);
    __syncthreads();

#pragma unroll
    for (int r = 0; r < 8; r++) {
        const ulonglong2* xv = (const ulonglong2*)(xs + r * 32);
        ull s0 = 0, s1 = 0;
#pragma unroll
        for (int q = 0; q < 8; q++) {
            ulonglong2 x2 = xv[q];
            s0 = fma2(x2.x, w2[2 * q], s0);
            s1 = fma2(x2.y, w2[2 * q + 1], s1);
        }
        d_gx[(blockIdx.x * 8 + r) * 256 + tid] = bsum + (sum2(s0) + sum2(s1));
    }
}

// ---------------- K2: LSTM recurrence (MUFU.TANH activations) ----------------
__global__ void __launch_bounds__(256) k2_lstm(const float* __restrict__ W_hh)
{
    __shared__ __align__(16) float h_s[64];
    __shared__ float gate_s[256];
    int t = threadIdx.x;
    int b = blockIdx.x;
    int grp = t >> 6;

    ull w2[32];
    const ull* wp = (const ull*)(W_hh + t * 64);
#pragma unroll
    for (int i = 0; i < 32; i++) w2[i] = wp[i];

    float c = 0.f;
    if (t < 64) h_s[t] = 0.f;
    float gx_c = d_gx[(0 * BATCH + b) * 256 + t];
    float gx_n = d_gx[(1 * BATCH + b) * 256 + t];
    __syncthreads();

    for (int step = 0; step < SEQ; step++) {
        float gx_f = 0.f;
        if (step + 2 < SEQ) gx_f = d_gx[((step + 2) * BATCH + b) * 256 + t];

        const ulonglong2* h2 = (const ulonglong2*)h_s;
        ull a0 = 0, a1 = 0, a2 = 0, a3 = 0;
#pragma unroll
        for (int i = 0; i < 8; i++) {
            ulonglong2 p = h2[2 * i], q = h2[2 * i + 1];
            a0 = fma2(p.x, w2[4 * i + 0], a0);
            a1 = fma2(p.y, w2[4 * i + 1], a1);
            a2 = fma2(q.x, w2[4 * i + 2], a2);
            a3 = fma2(q.y, w2[4 * i + 3], a3);
        }
        float gate = gx_c + ((sum2(a0) + sum2(a1)) + (sum2(a2) + sum2(a3)));
        float act = (grp == 2) ? tanh_mufu(gate) : sig_mufu(gate);
        gate_s[t] = act;
        __syncthreads();

        if (t < 64) {
            float ai = act;
            float af = gate_s[64 + t];
            float ag = gate_s[128 + t];
            float ao = gate_s[192 + t];
            c = af * c + ai * ag;
            float hv = ao * tanh_mufu(c);
            h_s[t] = hv;
            d_seq[(step * BATCH + b) * 64 + t] = hv;
        }
        __syncthreads();
        gx_c = gx_n; gx_n = gx_f;
    }
}

// ---------------- K3: QKV GEMM 128x64 tile, 256 thr, 8x4/thread ----------------
__global__ void __launch_bounds__(256) k3_qkv(
    const float* __restrict__ Wq, const float* __restrict__ bq,
    const float* __restrict__ Wk, const float* __restrict__ bk,
    const float* __restrict__ Wv, const float* __restrict__ bv)
{
    __shared__ __align__(16) float As[16 * 256];
    __shared__ __align__(16) float Bs[16 * 128];
    int tid = threadIdx.x;
    int mt = blockIdx.x, nt = blockIdx.y;

    const float* W; const float* bias; float* out; int n0;
    if (nt < 3)      { W = Wq; bias = bq; out = d_q; n0 = nt * 64; }
    else if (nt < 6) { W = Wk; bias = bk; out = d_k; n0 = (nt - 3) * 64; }
    else             { W = Wv; bias = bv; out = d_v; n0 = (nt - 6) * 64; }

    int tx = tid & 15, ty = tid >> 4;
    int m0 = ty * 8, nn0 = tx * 4;
    ull acc[8][4] = {};

    for (int kc = 0; kc < 2; kc++) {
#pragma unroll
        for (int i = 0; i < 4; i++) {
            int e = tid + i * 256;
            int r = e & 127, c4 = e >> 7;
            float4 v = *(const float4*)&d_seq[(mt * 128 + r) * 64 + kc * 32 + c4 * 4];
            *(float2*)&As[(c4 * 2) * 256 + r * 2] = make_float2(v.x, v.y);
            *(float2*)&As[(c4 * 2 + 1) * 256 + r * 2] = make_float2(v.z, v.w);
        }
#pragma unroll
        for (int i = 0; i < 2; i++) {
            int e = tid + i * 256;
            int r = e & 63, c4 = e >> 6;
            float4 v = *(const float4*)&W[(n0 + r) * 64 + kc * 32 + c4 * 4];
            *(float2*)&Bs[(c4 * 2) * 128 + r * 2] = make_float2(v.x, v.y);
            *(float2*)&Bs[(c4 * 2 + 1) * 128 + r * 2] = make_float2(v.z, v.w);
        }
        __syncthreads();
#pragma unroll
        for (int k2 = 0; k2 < 16; k2++) {
            ulonglong2 a01 = *(const ulonglong2*)&As[k2 * 256 + m0 * 2];
            ulonglong2 a23 = *(const ulonglong2*)&As[k2 * 256 + m0 * 2 + 4];
            ulonglong2 a45 = *(const ulonglong2*)&As[k2 * 256 + m0 * 2 + 8];
            ulonglong2 a67 = *(const ulonglong2*)&As[k2 * 256 + m0 * 2 + 12];
            ulonglong2 b01 = *(const ulonglong2*)&Bs[k2 * 128 + nn0 * 2];
            ulonglong2 b23 = *(const ulonglong2*)&Bs[k2 * 128 + nn0 * 2 + 4];
            ull av[8] = {a01.x, a01.y, a23.x, a23.y, a45.x, a45.y, a67.x, a67.y};
            ull bv_[4] = {b01.x, b01.y, b23.x, b23.y};
#pragma unroll
            for (int i = 0; i < 8; i++)
#pragma unroll
                for (int j = 0; j < 4; j++)
                    acc[i][j] = fma2(av[i], bv_[j], acc[i][j]);
        }
        __syncthreads();
    }
    float4 bv4 = *(const float4*)&bias[n0 + nn0];
#pragma unroll
    for (int i = 0; i < 8; i++) {
        int row = mt * 128 + m0 + i;
        float4 o;
        o.x = sum2(acc[i][0]) + bv4.x; o.y = sum2(acc[i][1]) + bv4.y;
        o.z = sum2(acc[i][2]) + bv4.z; o.w = sum2(acc[i][3]) + bv4.w;
        *(float4*)&out[row * EMB + n0 + nn0] = o;
    }
}

// ---------------- K4: attention (R3 proven layout: i = tid%40) ----------------
__global__ void __launch_bounds__(160) k4_attn()
{
    __shared__ __align__(16) float qs[40 * 52];
    __shared__ __align__(16) float ks[40 * 52];
    __shared__ __align__(16) float vs[40 * 52];
    __shared__ float ss[40 * 41];
    int t = blockIdx.x, h = blockIdx.y;
    int tid = threadIdx.x;

#pragma unroll
    for (int ii = 0; ii < 9; ii++) {
        int e = tid + ii * 160;
        int arr = e / 480, idx = e - arr * 480;
        int r = idx / 12, c4 = idx - r * 12;
        const float* src = arr == 0 ? d_q : (arr == 1 ? d_k : d_v);
        float* dst = arr == 0 ? qs : (arr == 1 ? ks : vs);
        float4 v = *(const float4*)&src[(t * BATCH + r) * EMB + h * DH + c4 * 4];
        *(float4*)&dst[r * 52 + c4 * 4] = v;
    }
    __syncthreads();

    int i = tid % 40;
    int ct = tid / 40;     // 0..3

    // S = Q K^T / 8 : each thread: row i vs 10 K-rows (K loads broadcast per warp)
    {
        int j0 = ct * 10;
        ull acc[10] = {};
#pragma unroll
        for (int kk = 0; kk < 12; kk++) {
            ulonglong2 q2 = *(const ulonglong2*)&qs[i * 52 + kk * 4];
#pragma unroll
            for (int jj = 0; jj < 10; jj++) {
                ulonglong2 k2v = *(const ulonglong2*)&ks[(j0 + jj) * 52 + kk * 4];
                acc[jj] = fma2(q2.x, k2v.x, acc[jj]);
                acc[jj] = fma2(q2.y, k2v.y, acc[jj]);
            }
        }
#pragma unroll
        for (int jj = 0; jj < 10; jj++)
            ss[i * 41 + j0 + jj] = sum2(acc[jj]) * 0.125f;
    }
    __syncthreads();

    if (tid < 40) {
        float m = -1e30f;
#pragma unroll
        for (int j = 0; j < 40; j++) m = fmaxf(m, ss[tid * 41 + j]);
        float p[40]; float sum = 0.f;
#pragma unroll
        for (int j = 0; j < 40; j++) { p[j] = __expf(ss[tid * 41 + j] - m); sum += p[j]; }
        float inv = 1.f / sum;
#pragma unroll
        for (int j = 0; j < 40; j++) ss[tid * 41 + j] = p[j] * inv;
    }
    __syncthreads();

    // O = P V : each thread: row i, d-chunk of 12 (V loads broadcast per warp)
    {
        int d0 = ct * 12;
        ull acc[6] = {};
#pragma unroll
        for (int j = 0; j < 40; j++) {
            ull sp = dup2(ss[i * 41 + j]);
            ulonglong2 v0 = *(const ulonglong2*)&vs[j * 52 + d0];
            ulonglong2 v1 = *(const ulonglong2*)&vs[j * 52 + d0 + 4];
            ulonglong2 v2 = *(const ulonglong2*)&vs[j * 52 + d0 + 8];
            acc[0] = fma2(sp, v0.x, acc[0]);
            acc[1] = fma2(sp, v0.y, acc[1]);
            acc[2] = fma2(sp, v1.x, acc[2]);
            acc[3] = fma2(sp, v1.y, acc[3]);
            acc[4] = fma2(sp, v2.x, acc[4]);
            acc[5] = fma2(sp, v2.y, acc[5]);
        }
        float* op = &d_att[(t * BATCH + i) * EMB + h * DH + d0];
        float4 o0, o1, o2;
        o0.x = lo32(acc[0]); o0.y = hi32(acc[0]); o0.z = lo32(acc[1]); o0.w = hi32(acc[1]);
        o1.x = lo32(acc[2]); o1.y = hi32(acc[2]); o1.z = lo32(acc[3]); o1.w = hi32(acc[3]);
        o2.x = lo32(acc[4]); o2.y = hi32(acc[4]); o2.z = lo32(acc[5]); o2.w = hi32(acc[5]);
        *(float4*)&op[0] = o0;
        *(float4*)&op[4] = o1;
        *(float4*)&op[8] = o2;
    }
}

// ---------------- K5: fused GLU GEMM (M64 x N128) + GLU + residual + LayerNorm ----------------
__global__ void __launch_bounds__(256) k5_glu_ln(
    const float* __restrict__ Wa, const float* __restrict__ ba,
    const float* __restrict__ Wg, const float* __restrict__ bg,
    const float* __restrict__ gamma, const float* __restrict__ beta,
    float* __restrict__ out)
{
    __shared__ __align__(16) float buf[64 * 136];
    float* As = buf;              // 16 x 128
    float* Bs = buf + 16 * 128;   // 16 x 256
    float* os = buf;              // 64 x 136 (reused after compute)
    int tid = threadIdx.x;
    int mt = blockIdx.x;

    int tx = tid & 31, ty = tid >> 5;
    int m0 = ty * 8, n0 = tx * 4;
    ull acc2[8][4] = {};

    for (int kc = 0; kc < 6; kc++) {
#pragma unroll
        for (int s = 0; s < 2; s++) {
            int e = tid + s * 256;
            int r = e & 63, c4 = e >> 6;
            float4 v = *(const float4*)&d_att[(mt * 64 + r) * EMB + kc * 32 + c4 * 4];
            *(float2*)&As[(c4 * 2) * 128 + r * 2] = make_float2(v.x, v.y);
            *(float2*)&As[(c4 * 2 + 1) * 128 + r * 2] = make_float2(v.z, v.w);
        }
#pragma unroll
        for (int s = 0; s < 4; s++) {
            int e = tid + s * 256;
            int r = e & 127, c4 = e >> 7;
            const float* Wsrc = (r < 64) ? &Wa[r * EMB] : &Wg[(r - 64) * EMB];
            float4 v = *(const float4*)&Wsrc[kc * 32 + c4 * 4];
            *(float2*)&Bs[(c4 * 2) * 256 + r * 2] = make_float2(v.x, v.y);
            *(float2*)&Bs[(c4 * 2 + 1) * 256 + r * 2] = make_float2(v.z, v.w);
        }
        __syncthreads();
#pragma unroll
        for (int k2 = 0; k2 < 16; k2++) {
            ulonglong2 a01 = *(const ulonglong2*)&As[k2 * 128 + m0 * 2];
            ulonglong2 a23 = *(const ulonglong2*)&As[k2 * 128 + m0 * 2 + 4];
            ulonglong2 a45 = *(const ulonglong2*)&As[k2 * 128 + m0 * 2 + 8];
            ulonglong2 a67 = *(const ulonglong2*)&As[k2 * 128 + m0 * 2 + 12];
            ulonglong2 b01 = *(const ulonglong2*)&Bs[k2 * 256 + n0 * 2];
            ulonglong2 b23 = *(const ulonglong2*)&Bs[k2 * 256 + n0 * 2 + 4];
            ull av[8] = {a01.x, a01.y, a23.x, a23.y, a45.x, a45.y, a67.x, a67.y};
            ull bv_[4] = {b01.x, b01.y, b23.x, b23.y};
#pragma unroll
            for (int i = 0; i < 8; i++)
#pragma unroll
                for (int j = 0; j < 4; j++)
                    acc2[i][j] = fma2(av[i], bv_[j], acc2[i][j]);
        }
        __syncthreads();
    }

    // write o (+bias) into os[64][136]
    float4 bv4;
    if (n0 < 64) bv4 = *(const float4*)&ba[n0];
    else         bv4 = *(const float4*)&bg[n0 - 64];
#pragma unroll
    for (int i = 0; i < 8; i++) {
        float4 o;
        o.x = sum2(acc2[i][0]) + bv4.x; o.y = sum2(acc2[i][1]) + bv4.y;
        o.z = sum2(acc2[i][2]) + bv4.z; o.w = sum2(acc2[i][3]) + bv4.w;
        *(float4*)&os[(m0 + i) * 136 + n0] = o;
    }
    __syncthreads();

    // GLU + residual + LayerNorm
    {
        int r = tid >> 2, q = tid & 3;
        int c0 = q * 16;
        int grow = mt * 64 + r;
        float y[16];
        float s = 0.f, s2 = 0.f;
#pragma unroll
        for (int c = 0; c < 16; c++) {
            int j = c0 + c;
            float a = os[r * 136 + j];
            float g = os[r * 136 + 64 + j];
            float yv = d_seq[grow * 64 + j] + a * sigf(g);
            y[c] = yv; s += yv; s2 += yv * yv;
        }
        s += __shfl_xor_sync(0xFFFFFFFFu, s, 1);
        s += __shfl_xor_sync(0xFFFFFFFFu, s, 2);
        s2 += __shfl_xor_sync(0xFFFFFFFFu, s2, 1);
        s2 += __shfl_xor_sync(0xFFFFFFFFu, s2, 2);
        float mu = s * (1.f / 64.f);
        float var = s2 * (1.f / 64.f) - mu * mu;
        float inv = rsqrtf(var + 1e-5f);
#pragma unroll
        for (int c = 0; c < 16; c++) {
            int j = c0 + c;
            out[grow * 64 + j] = (y[c] - mu) * inv * gamma[j] + beta[j];
        }
    }
}

// ---------------- launch ----------------
extern "C" void kernel_launch(void* const* d_in, const int* in_sizes, int n_in,
                              void* d_out, int out_size)
{
    const float* hist = (const float*)d_in[0];
    const float* W1   = (const float*)d_in[2];
    const float* b1   = (const float*)d_in[3];
    const float* W_ih = (const float*)d_in[4];
    const float* W_hh = (const float*)d_in[5];
    const float* b_ih = (const float*)d_in[6];
    const float* b_hh = (const float*)d_in[7];
    const float* Wq   = (const float*)d_in[8];
    const float* bq   = (const float*)d_in[9];
    const float* Wk   = (const float*)d_in[10];
    const float* bk   = (const float*)d_in[11];
    const float* Wv   = (const float*)d_in[12];
    const float* bv   = (const float*)d_in[13];
    const float* Wa   = (const float*)d_in[14];
    const float* ba   = (const float*)d_in[15];
    const float* Wg   = (const float*)d_in[16];
    const float* bg   = (const float*)d_in[17];
    const float* gamma= (const float*)d_in[18];
    const float* beta = (const float*)d_in[19];
    float* out = (float*)d_out;

    k1_embed_gates<<<ROWS / 8, 256>>>(hist, W1, b1, W_ih, b_ih, b_hh);
    k2_lstm<<<BATCH, 256>>>(W_hh);
    k3_qkv<<<dim3(ROWS / 128, 9), 256>>>(Wq, bq, Wk, bk, Wv, bv);
    k4_attn<<<dim3(SEQ, NH), 160>>>();
    k5_glu_ln<<<ROWS / 64, 256>>>(Wa, ba, Wg, bg, gamma, beta, out);
}

// round 6
// speedup vs baseline: 1.4640x; 1.2228x over previous
#include <cuda_runtime.h>
#include <math.h>

#define SEQ 640
#define BATCH 40
#define DIN 8
#define DL 64
#define NH 4
#define DH 48
#define EMB 192
#define ROWS (SEQ*BATCH)   // 25600

typedef unsigned long long ull;

// ---------------- scratch ----------------
__device__ float d_gx[ROWS * 256];
__device__ float d_seq[ROWS * DL];
__device__ float d_q[ROWS * EMB];
__device__ float d_k[ROWS * EMB];
__device__ float d_v[ROWS * EMB];
__device__ float d_att[ROWS * EMB];

__device__ __forceinline__ float sigf(float x) { return 1.f / (1.f + __expf(-x)); }

__device__ __forceinline__ float tanh_mufu(float x) {
    float y;
    asm("tanh.approx.f32 %0, %1;" : "=f"(y) : "f"(x));
    return y;
}
__device__ __forceinline__ float sig_mufu(float x) {
    return fmaf(tanh_mufu(0.5f * x), 0.5f, 0.5f);
}

__device__ __forceinline__ ull fma2(ull a, ull b, ull c) {
    ull d;
    asm("fma.rn.f32x2 %0, %1, %2, %3;" : "=l"(d) : "l"(a), "l"(b), "l"(c));
    return d;
}
__device__ __forceinline__ float lo32(ull u) { return __uint_as_float((unsigned)u); }
__device__ __forceinline__ float hi32(ull u) { return __uint_as_float((unsigned)(u >> 32)); }
__device__ __forceinline__ float sum2(ull u) { return lo32(u) + hi32(u); }
__device__ __forceinline__ ull dup2(float s) {
    ull d;
    asm("mov.b64 %0, {%1, %1};" : "=l"(d) : "r"(__float_as_uint(s)));
    return d;
}

// ---- tf32 mma helpers ----
__device__ __forceinline__ unsigned cvt_tf32(float x) {
    unsigned r;
    asm("cvt.rna.tf32.f32 %0, %1;" : "=r"(r) : "f"(x));
    return r;
}
__device__ __forceinline__ void mma_tf32(
    float& c0, float& c1, float& c2, float& c3,
    unsigned a0, unsigned a1, unsigned a2, unsigned a3,
    unsigned b0, unsigned b1)
{
    asm("mma.sync.aligned.m16n8k8.row.col.f32.tf32.tf32.f32 "
        "{%0,%1,%2,%3},{%4,%5,%6,%7},{%8,%9},{%0,%1,%2,%3};"
        : "+f"(c0), "+f"(c1), "+f"(c2), "+f"(c3)
        : "r"(a0), "r"(a1), "r"(a2), "r"(a3), "r"(b0), "r"(b1));
}

// ---------------- K1: embed + gates_x ----------------
__global__ void __launch_bounds__(256) k1_embed_gates(
    const float* __restrict__ hist, const float* __restrict__ W1,
    const float* __restrict__ b1, const float* __restrict__ W_ih,
    const float* __restrict__ b_ih, const float* __restrict__ b_hh)
{
    __shared__ __align__(16) float xs[8 * 32];
    int tid = threadIdx.x;

    ull w2[16];
    const ull* wp = (const ull*)(W_ih + tid * 32);
#pragma unroll
    for (int i = 0; i < 16; i++) w2[i] = wp[i];
    float bsum = b_ih[tid] + b_hh[tid];

    int rl = tid >> 5, j = tid & 31;
    const float* hp = hist + (blockIdx.x * 8 + rl) * DIN;
    float acc = b1[j];
#pragma unroll
    for (int f = 0; f < DIN; f++) acc = fmaf(hp[f], W1[j * DIN + f], acc);
    xs[rl * 32 + j] = acc > 0.f ? acc : expm1f(acc);
    __syncthreads();

#pragma unroll
    for (int r = 0; r < 8; r++) {
        const ulonglong2* xv = (const ulonglong2*)(xs + r * 32);
        ull s0 = 0, s1 = 0;
#pragma unroll
        for (int q = 0; q < 8; q++) {
            ulonglong2 x2 = xv[q];
            s0 = fma2(x2.x, w2[2 * q], s0);
            s1 = fma2(x2.y, w2[2 * q + 1], s1);
        }
        d_gx[(blockIdx.x * 8 + r) * 256 + tid] = bsum + (sum2(s0) + sum2(s1));
    }
}

// ---------------- K2: LSTM recurrence (MUFU.TANH) ----------------
__global__ void __launch_bounds__(256) k2_lstm(const float* __restrict__ W_hh)
{
    __shared__ __align__(16) float h_s[64];
    __shared__ float gate_s[256];
    int t = threadIdx.x;
    int b = blockIdx.x;
    int grp = t >> 6;

    ull w2[32];
    const ull* wp = (const ull*)(W_hh + t * 64);
#pragma unroll
    for (int i = 0; i < 32; i++) w2[i] = wp[i];

    float c = 0.f;
    if (t < 64) h_s[t] = 0.f;
    float gx_c = d_gx[(0 * BATCH + b) * 256 + t];
    float gx_n = d_gx[(1 * BATCH + b) * 256 + t];
    __syncthreads();

    for (int step = 0; step < SEQ; step++) {
        float gx_f = 0.f;
        if (step + 2 < SEQ) gx_f = d_gx[((step + 2) * BATCH + b) * 256 + t];

        const ulonglong2* h2 = (const ulonglong2*)h_s;
        ull a0 = 0, a1 = 0, a2 = 0, a3 = 0;
#pragma unroll
        for (int i = 0; i < 8; i++) {
            ulonglong2 p = h2[2 * i], q = h2[2 * i + 1];
            a0 = fma2(p.x, w2[4 * i + 0], a0);
            a1 = fma2(p.y, w2[4 * i + 1], a1);
            a2 = fma2(q.x, w2[4 * i + 2], a2);
            a3 = fma2(q.y, w2[4 * i + 3], a3);
        }
        float gate = gx_c + ((sum2(a0) + sum2(a1)) + (sum2(a2) + sum2(a3)));
        float act = (grp == 2) ? tanh_mufu(gate) : sig_mufu(gate);
        gate_s[t] = act;
        __syncthreads();

        if (t < 64) {
            float ai = act;
            float af = gate_s[64 + t];
            float ag = gate_s[128 + t];
            float ao = gate_s[192 + t];
            c = af * c + ai * ag;
            float hv = ao * tanh_mufu(c);
            h_s[t] = hv;
            d_seq[(step * BATCH + b) * 64 + t] = hv;
        }
        __syncthreads();
        gx_c = gx_n; gx_n = gx_f;
    }
}

// ---------------- K3: QKV GEMM via tf32 mma.sync, M64 x N64 per block ----------------
__global__ void __launch_bounds__(256) k3_qkv(
    const float* __restrict__ Wq, const float* __restrict__ bq,
    const float* __restrict__ Wk, const float* __restrict__ bk,
    const float* __restrict__ Wv, const float* __restrict__ bv)
{
    __shared__ unsigned As[64 * 68];   // [m][k] tf32
    __shared__ unsigned Bs[64 * 68];   // [n][k] tf32
    int tid = threadIdx.x;
    int mt = blockIdx.x, nt = blockIdx.y;

    const float* W; const float* bias; float* out; int n0;
    if (nt < 3)      { W = Wq; bias = bq; out = d_q; n0 = nt * 64; }
    else if (nt < 6) { W = Wk; bias = bk; out = d_k; n0 = (nt - 3) * 64; }
    else             { W = Wv; bias = bv; out = d_v; n0 = (nt - 6) * 64; }

#pragma unroll
    for (int s = 0; s < 4; s++) {
        int e = tid + s * 256;
        int r = e >> 4, c4 = e & 15;
        float4 v = *(const float4*)&d_seq[(mt * 64 + r) * 64 + c4 * 4];
        uint4 u = make_uint4(cvt_tf32(v.x), cvt_tf32(v.y), cvt_tf32(v.z), cvt_tf32(v.w));
        *(uint4*)&As[r * 68 + c4 * 4] = u;
    }
#pragma unroll
    for (int s = 0; s < 4; s++) {
        int e = tid + s * 256;
        int r = e >> 4, c4 = e & 15;
        float4 v = *(const float4*)&W[(n0 + r) * 64 + c4 * 4];
        uint4 u = make_uint4(cvt_tf32(v.x), cvt_tf32(v.y), cvt_tf32(v.z), cvt_tf32(v.w));
        *(uint4*)&Bs[r * 68 + c4 * 4] = u;
    }
    __syncthreads();

    int lane = tid & 31, wid = tid >> 5;
    int wm = wid >> 1, wn = wid & 1;         // 4 m-warps x 2 n-warps
    int g = lane >> 2, tg = lane & 3;

    float acc[4][4] = {};
    int ar0 = (wm * 16 + g) * 68;
    int ar1 = ar0 + 8 * 68;
#pragma unroll
    for (int k8 = 0; k8 < 8; k8++) {
        int kb = k8 * 8 + tg;
        unsigned a0 = As[ar0 + kb];
        unsigned a1 = As[ar1 + kb];
        unsigned a2 = As[ar0 + kb + 4];
        unsigned a3 = As[ar1 + kb + 4];
#pragma unroll
        for (int ntl = 0; ntl < 4; ntl++) {
            int bb = (wn * 32 + ntl * 8 + g) * 68 + kb;
            unsigned b0 = Bs[bb];
            unsigned b1 = Bs[bb + 4];
            mma_tf32(acc[ntl][0], acc[ntl][1], acc[ntl][2], acc[ntl][3],
                     a0, a1, a2, a3, b0, b1);
        }
    }

#pragma unroll
    for (int ntl = 0; ntl < 4; ntl++) {
        int col = n0 + wn * 32 + ntl * 8 + 2 * tg;
        float2 b2 = *(const float2*)&bias[col];
        int row0 = mt * 64 + wm * 16 + g;
        float2 o0 = make_float2(acc[ntl][0] + b2.x, acc[ntl][1] + b2.y);
        float2 o1 = make_float2(acc[ntl][2] + b2.x, acc[ntl][3] + b2.y);
        *(float2*)&out[row0 * EMB + col] = o0;
        *(float2*)&out[(row0 + 8) * EMB + col] = o1;
    }
}

// ---------------- K4: attention (R3 proven layout) ----------------
__global__ void __launch_bounds__(160) k4_attn()
{
    __shared__ __align__(16) float qs[40 * 52];
    __shared__ __align__(16) float ks[40 * 52];
    __shared__ __align__(16) float vs[40 * 52];
    __shared__ float ss[40 * 41];
    int t = blockIdx.x, h = blockIdx.y;
    int tid = threadIdx.x;

#pragma unroll
    for (int ii = 0; ii < 9; ii++) {
        int e = tid + ii * 160;
        int arr = e / 480, idx = e - arr * 480;
        int r = idx / 12, c4 = idx - r * 12;
        const float* src = arr == 0 ? d_q : (arr == 1 ? d_k : d_v);
        float* dst = arr == 0 ? qs : (arr == 1 ? ks : vs);
        float4 v = *(const float4*)&src[(t * BATCH + r) * EMB + h * DH + c4 * 4];
        *(float4*)&dst[r * 52 + c4 * 4] = v;
    }
    __syncthreads();

    int i = tid % 40;
    int ct = tid / 40;

    {
        int j0 = ct * 10;
        ull acc[10] = {};
#pragma unroll
        for (int kk = 0; kk < 12; kk++) {
            ulonglong2 q2 = *(const ulonglong2*)&qs[i * 52 + kk * 4];
#pragma unroll
            for (int jj = 0; jj < 10; jj++) {
                ulonglong2 k2v = *(const ulonglong2*)&ks[(j0 + jj) * 52 + kk * 4];
                acc[jj] = fma2(q2.x, k2v.x, acc[jj]);
                acc[jj] = fma2(q2.y, k2v.y, acc[jj]);
            }
        }
#pragma unroll
        for (int jj = 0; jj < 10; jj++)
            ss[i * 41 + j0 + jj] = sum2(acc[jj]) * 0.125f;
    }
    __syncthreads();

    if (tid < 40) {
        float m = -1e30f;
#pragma unroll
        for (int j = 0; j < 40; j++) m = fmaxf(m, ss[tid * 41 + j]);
        float p[40]; float sum = 0.f;
#pragma unroll
        for (int j = 0; j < 40; j++) { p[j] = __expf(ss[tid * 41 + j] - m); sum += p[j]; }
        float inv = 1.f / sum;
#pragma unroll
        for (int j = 0; j < 40; j++) ss[tid * 41 + j] = p[j] * inv;
    }
    __syncthreads();

    {
        int d0 = ct * 12;
        ull acc[6] = {};
#pragma unroll
        for (int j = 0; j < 40; j++) {
            ull sp = dup2(ss[i * 41 + j]);
            ulonglong2 v0 = *(const ulonglong2*)&vs[j * 52 + d0];
            ulonglong2 v1 = *(const ulonglong2*)&vs[j * 52 + d0 + 4];
            ulonglong2 v2 = *(const ulonglong2*)&vs[j * 52 + d0 + 8];
            acc[0] = fma2(sp, v0.x, acc[0]);
            acc[1] = fma2(sp, v0.y, acc[1]);
            acc[2] = fma2(sp, v1.x, acc[2]);
            acc[3] = fma2(sp, v1.y, acc[3]);
            acc[4] = fma2(sp, v2.x, acc[4]);
            acc[5] = fma2(sp, v2.y, acc[5]);
        }
        float* op = &d_att[(t * BATCH + i) * EMB + h * DH + d0];
        float4 o0, o1, o2;
        o0.x = lo32(acc[0]); o0.y = hi32(acc[0]); o0.z = lo32(acc[1]); o0.w = hi32(acc[1]);
        o1.x = lo32(acc[2]); o1.y = hi32(acc[2]); o1.z = lo32(acc[3]); o1.w = hi32(acc[3]);
        o2.x = lo32(acc[4]); o2.y = hi32(acc[4]); o2.z = lo32(acc[5]); o2.w = hi32(acc[5]);
        *(float4*)&op[0] = o0;
        *(float4*)&op[4] = o1;
        *(float4*)&op[8] = o2;
    }
}

// ---------------- K5: tf32 mma GLU GEMM (M64 x N128, K192) + GLU + residual + LN ----------------
__global__ void __launch_bounds__(256) k5_glu_ln(
    const float* __restrict__ Wa, const float* __restrict__ ba,
    const float* __restrict__ Wg, const float* __restrict__ bg,
    const float* __restrict__ gamma, const float* __restrict__ beta,
    float* __restrict__ out)
{
    __shared__ __align__(16) float buf[64 * 136];     // 34.8 KB, overlaid
    unsigned* As = (unsigned*)buf;                    // 64 x 36
    unsigned* Bs = (unsigned*)buf + 64 * 36;          // 128 x 36
    float* os = buf;                                  // 64 x 136 epilogue
    int tid = threadIdx.x;
    int mt = blockIdx.x;

    int lane = tid & 31, wid = tid >> 5;
    int wm = wid >> 2, wn = wid & 3;     // 2 m-warps x 4 n-warps
    int g = lane >> 2, tg = lane & 3;

    float acc[2][4][4] = {};

    for (int kc = 0; kc < 6; kc++) {
#pragma unroll
        for (int s = 0; s < 2; s++) {
            int e = tid + s * 256;
            int r = e >> 3, c4 = e & 7;
            float4 v = *(const float4*)&d_att[(mt * 64 + r) * EMB + kc * 32 + c4 * 4];
            uint4 u = make_uint4(cvt_tf32(v.x), cvt_tf32(v.y), cvt_tf32(v.z), cvt_tf32(v.w));
            *(uint4*)&As[r * 36 + c4 * 4] = u;
        }
#pragma unroll
        for (int s = 0; s < 4; s++) {
            int e = tid + s * 256;
            int r = e >> 3, c4 = e & 7;
            const float* Wsrc = (r < 64) ? &Wa[r * EMB] : &Wg[(r - 64) * EMB];
            float4 v = *(const float4*)&Wsrc[kc * 32 + c4 * 4];
            uint4 u = make_uint4(cvt_tf32(v.x), cvt_tf32(v.y), cvt_tf32(v.z), cvt_tf32(v.w));
            *(uint4*)&Bs[r * 36 + c4 * 4] = u;
        }
        __syncthreads();

#pragma unroll
        for (int k8 = 0; k8 < 4; k8++) {
            int kb = k8 * 8 + tg;
            unsigned a[2][4];
#pragma unroll
            for (int mtl = 0; mtl < 2; mtl++) {
                int ar0 = (wm * 32 + mtl * 16 + g) * 36;
                a[mtl][0] = As[ar0 + kb];
                a[mtl][1] = As[ar0 + 8 * 36 + kb];
                a[mtl][2] = As[ar0 + kb + 4];
                a[mtl][3] = As[ar0 + 8 * 36 + kb + 4];
            }
#pragma unroll
            for (int ntl = 0; ntl < 4; ntl++) {
                int bb = (wn * 32 + ntl * 8 + g) * 36 + kb;
                unsigned b0 = Bs[bb];
                unsigned b1 = Bs[bb + 4];
#pragma unroll
                for (int mtl = 0; mtl < 2; mtl++)
                    mma_tf32(acc[mtl][ntl][0], acc[mtl][ntl][1],
                             acc[mtl][ntl][2], acc[mtl][ntl][3],
                             a[mtl][0], a[mtl][1], a[mtl][2], a[mtl][3], b0, b1);
            }
        }
        __syncthreads();
    }

    // write o (+bias) into os[64][136]
#pragma unroll
    for (int mtl = 0; mtl < 2; mtl++) {
#pragma unroll
        for (int ntl = 0; ntl < 4; ntl++) {
            int col = wn * 32 + ntl * 8 + 2 * tg;
            float2 b2 = (col < 64) ? *(const float2*)&ba[col]
                                   : *(const float2*)&bg[col - 64];
            int row0 = wm * 32 + mtl * 16 + g;
            os[row0 * 136 + col]     = acc[mtl][ntl][0] + b2.x;
            os[row0 * 136 + col + 1] = acc[mtl][ntl][1] + b2.y;
            os[(row0 + 8) * 136 + col]     = acc[mtl][ntl][2] + b2.x;
            os[(row0 + 8) * 136 + col + 1] = acc[mtl][ntl][3] + b2.y;
        }
    }
    __syncthreads();

    // GLU + residual + LayerNorm
    {
        int r = tid >> 2, q = tid & 3;
        int c0 = q * 16;
        int grow = mt * 64 + r;
        float y[16];
        float s = 0.f, s2 = 0.f;
#pragma unroll
        for (int c = 0; c < 16; c++) {
            int j = c0 + c;
            float a = os[r * 136 + j];
            float g2 = os[r * 136 + 64 + j];
            float yv = d_seq[grow * 64 + j] + a * sigf(g2);
            y[c] = yv; s += yv; s2 += yv * yv;
        }
        s += __shfl_xor_sync(0xFFFFFFFFu, s, 1);
        s += __shfl_xor_sync(0xFFFFFFFFu, s, 2);
        s2 += __shfl_xor_sync(0xFFFFFFFFu, s2, 1);
        s2 += __shfl_xor_sync(0xFFFFFFFFu, s2, 2);
        float mu = s * (1.f / 64.f);
        float var = s2 * (1.f / 64.f) - mu * mu;
        float inv = rsqrtf(var + 1e-5f);
#pragma unroll
        for (int c = 0; c < 16; c++) {
            int j = c0 + c;
            out[grow * 64 + j] = (y[c] - mu) * inv * gamma[j] + beta[j];
        }
    }
}

// ---------------- launch ----------------
extern "C" void kernel_launch(void* const* d_in, const int* in_sizes, int n_in,
                              void* d_out, int out_size)
{
    const float* hist = (const float*)d_in[0];
    const float* W1   = (const float*)d_in[2];
    const float* b1   = (const float*)d_in[3];
    const float* W_ih = (const float*)d_in[4];
    const float* W_hh = (const float*)d_in[5];
    const float* b_ih = (const float*)d_in[6];
    const float* b_hh = (const float*)d_in[7];
    const float* Wq   = (const float*)d_in[8];
    const float* bq   = (const float*)d_in[9];
    const float* Wk   = (const float*)d_in[10];
    const float* bk   = (const float*)d_in[11];
    const float* Wv   = (const float*)d_in[12];
    const float* bv   = (const float*)d_in[13];
    const float* Wa   = (const float*)d_in[14];
    const float* ba   = (const float*)d_in[15];
    const float* Wg   = (const float*)d_in[16];
    const float* bg   = (const float*)d_in[17];
    const float* gamma= (const float*)d_in[18];
    const float* beta = (const float*)d_in[19];
    float* out = (float*)d_out;

    k1_embed_gates<<<ROWS / 8, 256>>>(hist, W1, b1, W_ih, b_ih, b_hh);
    k2_lstm<<<BATCH, 256>>>(W_hh);
    k3_qkv<<<dim3(ROWS / 64, 9), 256>>>(Wq, bq, Wk, bk, Wv, bv);
    k4_attn<<<dim3(SEQ, NH), 160>>>();
    k5_glu_ln<<<ROWS / 64, 256>>>(Wa, ba, Wg, bg, gamma, beta, out);
}